// round 4
// baseline (speedup 1.0000x reference)
#include <cuda_runtime.h>

// SlidingVariance: x (B=32, L=16384, C=1) fp32, w=64.
// out[b,i] = population variance of x[b, i : min(i+w, L)].
//
// Direct-from-global register windows: each thread loads its 68-element
// window as 17 float4 LDGs (independent -> MLP=17, L1-hit heavy from
// neighbor-thread overlap), computes 4 outputs via rolling sums.
// No shared memory, no __syncthreads.

#define W       64
#define OPT     4
#define THREADS 128
#define TILE    (THREADS * OPT)   // 512
#define NV4     (W / 4 + 1)       // 17 float4 per thread

__global__ __launch_bounds__(THREADS)
void sliding_var_kernel(const float* __restrict__ x,
                        float* __restrict__ out,
                        int L) {
    const int b  = blockIdx.y;
    const int t0 = blockIdx.x * TILE;
    const float* xb = x + (long)b * L;

    const int i = t0 + threadIdx.x * OPT;   // first output index, i % 4 == 0

    float4 v[NV4];
    if (t0 + TILE + W <= L) {
        // Fast path: whole window run in-bounds.
        const float4* p = reinterpret_cast<const float4*>(xb + i);
        #pragma unroll
        for (int j = 0; j < NV4; j++) v[j] = p[j];
    } else {
        // Tail: guarded loads, zero past L.
        #pragma unroll
        for (int j = 0; j < NV4; j++) {
            int idx = i + j * 4;
            if (idx + 3 < L) {
                v[j] = *reinterpret_cast<const float4*>(xb + idx);
            } else {
                v[j].x = (idx + 0 < L) ? xb[idx + 0] : 0.0f;
                v[j].y = (idx + 1 < L) ? xb[idx + 1] : 0.0f;
                v[j].z = (idx + 2 < L) ? xb[idx + 2] : 0.0f;
                v[j].w = (idx + 3 < L) ? xb[idx + 3] : 0.0f;
            }
        }
    }

    // Initial window sums over v[0..15]; two accumulator pairs to
    // shorten dependency chains.
    float sA = 0.0f, sB = 0.0f, qA = 0.0f, qB = 0.0f;
    #pragma unroll
    for (int j = 0; j < W / 4; j += 2) {
        float4 u = v[j];
        float4 t = v[j + 1];
        sA += (u.x + u.y) + (u.z + u.w);
        sB += (t.x + t.y) + (t.z + t.w);
        qA = fmaf(u.x, u.x, qA);
        qA = fmaf(u.y, u.y, qA);
        qA = fmaf(u.z, u.z, qA);
        qA = fmaf(u.w, u.w, qA);
        qB = fmaf(t.x, t.x, qB);
        qB = fmaf(t.y, t.y, qB);
        qB = fmaf(t.z, t.z, qB);
        qB = fmaf(t.w, t.w, qB);
    }
    float s  = sA + sB;
    float s2 = qA + qB;

    // Rolling updates for outputs i+1..i+3.
    float sv[OPT], qv[OPT];
    sv[0] = s; qv[0] = s2;
    {
        float vold, vnew;
        vold = v[0].x; vnew = v[16].x;
        s += vnew - vold; s2 = fmaf(vnew, vnew, fmaf(-vold, vold, s2));
        sv[1] = s; qv[1] = s2;
        vold = v[0].y; vnew = v[16].y;
        s += vnew - vold; s2 = fmaf(vnew, vnew, fmaf(-vold, vold, s2));
        sv[2] = s; qv[2] = s2;
        vold = v[0].z; vnew = v[16].z;
        s += vnew - vold; s2 = fmaf(vnew, vnew, fmaf(-vold, vold, s2));
        sv[3] = s; qv[3] = s2;
    }

    // Epilogue: variance = s2/n - (s/n)^2.
    float4 o;
    float* ro = reinterpret_cast<float*>(&o);
    if (i + OPT - 1 + W <= L) {
        const float inv = 1.0f / (float)W;
        #pragma unroll
        for (int k = 0; k < OPT; k++) {
            float m = sv[k] * inv;
            ro[k] = fmaf(-m, m, qv[k] * inv);
        }
    } else {
        #pragma unroll
        for (int k = 0; k < OPT; k++) {
            int ii = i + k;
            if (ii < L) {
                int n = min(W, L - ii);
                float inv = 1.0f / (float)n;
                float m = sv[k] * inv;
                ro[k] = fmaf(-m, m, qv[k] * inv);
            } else {
                ro[k] = 0.0f;
            }
        }
    }

    // L % TILE == 0: all OPT outputs valid.
    *reinterpret_cast<float4*>(out + (long)b * L + i) = o;
}

extern "C" void kernel_launch(void* const* d_in, const int* in_sizes, int n_in,
                              void* d_out, int out_size) {
    const float* x = (const float*)d_in[0];
    float* out = (float*)d_out;

    const int B = 32;
    const int L = 16384;

    dim3 grid((L + TILE - 1) / TILE, B);   // (32, 32) = 1024 blocks
    sliding_var_kernel<<<grid, THREADS>>>(x, out, L);
}

// round 5
// speedup vs baseline: 1.2977x; 1.2977x over previous
#include <cuda_runtime.h>

// SlidingVariance: x (B=32, L=16384, C=1) fp32, w=64.
// out[b,i] = population variance of x[b, i : min(i+w, L)].
//
// Block prefix-sum formulation: stage 512 elements (zero-filled past L),
// build exclusive prefix sums of x and x^2 (register chunk-4 + warp shuffle
// scan + cross-warp fixup), then each window sum is P[o+64]-P[o].
// 448 outputs per block (tiles overlap by W).

#define W        64
#define THREADS  128
#define CHUNK    4
#define STAGE    (THREADS * CHUNK)     // 512
#define OUT_TILE (STAGE - W)           // 448

__global__ __launch_bounds__(THREADS)
void sliding_var_kernel(const float* __restrict__ x,
                        float* __restrict__ out,
                        int L) {
    __shared__ float Ps[STAGE];
    __shared__ float Pq[STAGE];
    __shared__ float wsum_s[4];
    __shared__ float wsum_q[4];

    const int b  = blockIdx.y;
    const int t0 = blockIdx.x * OUT_TILE;          // multiple of 4
    const float* xb = x + (long)b * L;

    const int t    = threadIdx.x;
    const int lane = t & 31;
    const int wid  = t >> 5;

    // ---- Load this thread's 4-element chunk (zero past L) ----
    const int idx = t0 + CHUNK * t;
    float4 v;
    if (idx + 3 < L) {
        v = *reinterpret_cast<const float4*>(xb + idx);
    } else {
        v.x = (idx + 0 < L) ? xb[idx + 0] : 0.0f;
        v.y = (idx + 1 < L) ? xb[idx + 1] : 0.0f;
        v.z = (idx + 2 < L) ? xb[idx + 2] : 0.0f;
        v.w = (idx + 3 < L) ? xb[idx + 3] : 0.0f;
    }

    // ---- Local inclusive prefixes within the chunk ----
    float s1 = v.x;
    float s2 = s1 + v.y;
    float s3 = s2 + v.z;
    float cs = s3 + v.w;                 // chunk sum
    float q1 = v.x * v.x;
    float q2 = fmaf(v.y, v.y, q1);
    float q3 = fmaf(v.z, v.z, q2);
    float cq = fmaf(v.w, v.w, q3);       // chunk sum of squares

    // ---- Warp inclusive scan of chunk sums ----
    float scan_s = cs, scan_q = cq;
    #pragma unroll
    for (int o = 1; o < 32; o <<= 1) {
        float as = __shfl_up_sync(0xFFFFFFFFu, scan_s, o);
        float aq = __shfl_up_sync(0xFFFFFFFFu, scan_q, o);
        if (lane >= o) { scan_s += as; scan_q += aq; }
    }
    if (lane == 31) { wsum_s[wid] = scan_s; wsum_q[wid] = scan_q; }
    __syncthreads();

    // ---- Cross-warp offsets (only 4 warps) ----
    float off_s = 0.0f, off_q = 0.0f;
    #pragma unroll
    for (int w2 = 0; w2 < 3; w2++) {
        if (w2 < wid) { off_s += wsum_s[w2]; off_q += wsum_q[w2]; }
    }

    // Exclusive prefix at this thread's chunk start.
    float Es = off_s + (scan_s - cs);
    float Eq = off_q + (scan_q - cq);

    // ---- Write element-granularity exclusive prefixes ----
    float4 ps = make_float4(Es, Es + s1, Es + s2, Es + s3);
    float4 pq = make_float4(Eq, Eq + q1, Eq + q2, Eq + q3);
    *reinterpret_cast<float4*>(&Ps[CHUNK * t]) = ps;
    *reinterpret_cast<float4*>(&Pq[CHUNK * t]) = pq;
    __syncthreads();

    // ---- Epilogue: 4 outputs per thread (threads 0..111) ----
    if (t < OUT_TILE / CHUNK) {
        const int o = CHUNK * t;
        const int i = t0 + o;
        if (i < L) {
            float4 ls = *reinterpret_cast<const float4*>(&Ps[o]);
            float4 hs = *reinterpret_cast<const float4*>(&Ps[o + W]);
            float4 lq = *reinterpret_cast<const float4*>(&Pq[o]);
            float4 hq = *reinterpret_cast<const float4*>(&Pq[o + W]);

            float sw[4] = {hs.x - ls.x, hs.y - ls.y, hs.z - ls.z, hs.w - ls.w};
            float qw[4] = {hq.x - lq.x, hq.y - lq.y, hq.z - lq.z, hq.w - lq.w};

            float4 res;
            float* ro = reinterpret_cast<float*>(&res);
            if (i + 3 + W <= L) {
                const float inv = 1.0f / (float)W;
                #pragma unroll
                for (int k = 0; k < 4; k++) {
                    float m = sw[k] * inv;
                    ro[k] = fmaf(-m, m, qw[k] * inv);
                }
            } else {
                #pragma unroll
                for (int k = 0; k < 4; k++) {
                    int n = min(W, L - (i + k));   // i+k < L holds (L%4==0)
                    float inv = 1.0f / (float)n;
                    float m = sw[k] * inv;
                    ro[k] = fmaf(-m, m, qw[k] * inv);
                }
            }
            // i%4==0 and i<L with L%4==0 -> all 4 lanes valid.
            *reinterpret_cast<float4*>(out + (long)b * L + i) = res;
        }
    }
}

extern "C" void kernel_launch(void* const* d_in, const int* in_sizes, int n_in,
                              void* d_out, int out_size) {
    const float* x = (const float*)d_in[0];
    float* out = (float*)d_out;

    const int B = 32;
    const int L = 16384;

    dim3 grid((L + OUT_TILE - 1) / OUT_TILE, B);   // (37, 32) = 1184 blocks
    sliding_var_kernel<<<grid, THREADS>>>(x, out, L);
}

// round 6
// speedup vs baseline: 1.3478x; 1.0386x over previous
#include <cuda_runtime.h>

// SlidingVariance: x (B=32, L=16384, C=1) fp32, w=64.
// out[b,i] = population variance of x[b, i : min(i+w, L)].
//
// Warp-local prefix-sum formulation, CHUNK=2 so one warp spans exactly
// W=64 elements. Then for any output offset o:
//   windowsum(o) = rawP[o+64] - rawP[o] + warpsum[o/64]
// where rawP is the within-warp exclusive prefix (no cross-warp scan
// needed at all). One barrier, 256 threads, 8 warps/block, 64 warps/SM.

#define W        64
#define THREADS  256
#define CHUNK    2
#define STAGE    (THREADS * CHUNK)     // 512
#define OUT_TILE (STAGE - W)           // 448

__global__ __launch_bounds__(THREADS, 8)
void sliding_var_kernel(const float* __restrict__ x,
                        float* __restrict__ out,
                        int L) {
    __shared__ float Ps[STAGE];
    __shared__ float Pq[STAGE];
    __shared__ float wsum_s[THREADS / 32];   // 8
    __shared__ float wsum_q[THREADS / 32];

    const int b  = blockIdx.y;
    const int t0 = blockIdx.x * OUT_TILE;
    const float* xb = x + (long)b * L;

    const int t    = threadIdx.x;
    const int lane = t & 31;
    const int wid  = t >> 5;

    // ---- Load 2 elements (zero past L) ----
    const int idx = t0 + CHUNK * t;
    float2 v;
    if (idx + 1 < L) {
        v = *reinterpret_cast<const float2*>(xb + idx);
    } else {
        v.x = (idx + 0 < L) ? xb[idx + 0] : 0.0f;
        v.y = (idx + 1 < L) ? xb[idx + 1] : 0.0f;
    }

    const float s1 = v.x;
    const float cs = v.x + v.y;
    const float q1 = v.x * v.x;
    const float cq = fmaf(v.y, v.y, q1);

    // ---- Warp inclusive scan of chunk sums ----
    float scan_s = cs, scan_q = cq;
    #pragma unroll
    for (int o = 1; o < 32; o <<= 1) {
        float as = __shfl_up_sync(0xFFFFFFFFu, scan_s, o);
        float aq = __shfl_up_sync(0xFFFFFFFFu, scan_q, o);
        if (lane >= o) { scan_s += as; scan_q += aq; }
    }

    // Within-warp exclusive prefixes at element granularity (RAW: no
    // cross-warp offset applied — the epilogue identity absorbs it).
    const float Es = scan_s - cs;
    const float Eq = scan_q - cq;
    *reinterpret_cast<float2*>(&Ps[CHUNK * t]) = make_float2(Es, Es + s1);
    *reinterpret_cast<float2*>(&Pq[CHUNK * t]) = make_float2(Eq, Eq + q1);
    if (lane == 31) { wsum_s[wid] = scan_s; wsum_q[wid] = scan_q; }
    __syncthreads();

    // ---- Epilogue: 2 outputs per thread (threads 0..223) ----
    if (t < OUT_TILE / CHUNK) {
        const int o = CHUNK * t;
        const int i = t0 + o;
        if (i < L) {
            // windowsum = rawP[o+W] - rawP[o] + warpsum[o>>6]
            const float ds = wsum_s[o >> 6];   // warp-uniform -> broadcast
            const float dq = wsum_q[o >> 6];
            float2 lo_s = *reinterpret_cast<const float2*>(&Ps[o]);
            float2 hi_s = *reinterpret_cast<const float2*>(&Ps[o + W]);
            float2 lo_q = *reinterpret_cast<const float2*>(&Pq[o]);
            float2 hi_q = *reinterpret_cast<const float2*>(&Pq[o + W]);

            float sw0 = hi_s.x - lo_s.x + ds;
            float sw1 = hi_s.y - lo_s.y + ds;
            float qw0 = hi_q.x - lo_q.x + dq;
            float qw1 = hi_q.y - lo_q.y + dq;

            float2 res;
            if (i + 1 + W <= L) {
                const float inv = 1.0f / (float)W;
                float m0 = sw0 * inv;
                float m1 = sw1 * inv;
                res.x = fmaf(-m0, m0, qw0 * inv);
                res.y = fmaf(-m1, m1, qw1 * inv);
            } else {
                int n0 = min(W, L - i);
                int n1 = min(W, L - (i + 1));   // i+1 < L since L even, i even
                float inv0 = 1.0f / (float)n0;
                float inv1 = 1.0f / (float)n1;
                float m0 = sw0 * inv0;
                float m1 = sw1 * inv1;
                res.x = fmaf(-m0, m0, qw0 * inv0);
                res.y = fmaf(-m1, m1, qw1 * inv1);
            }
            *reinterpret_cast<float2*>(out + (long)b * L + i) = res;
        }
    }
}

extern "C" void kernel_launch(void* const* d_in, const int* in_sizes, int n_in,
                              void* d_out, int out_size) {
    const float* x = (const float*)d_in[0];
    float* out = (float*)d_out;

    const int B = 32;
    const int L = 16384;

    dim3 grid((L + OUT_TILE - 1) / OUT_TILE, B);   // (37, 32) = 1184 blocks
    sliding_var_kernel<<<grid, THREADS>>>(x, out, L);
}